// round 4
// baseline (speedup 1.0000x reference)
#include <cuda_runtime.h>

#define NMAX 100000
#define EMAX 1600000

typedef unsigned long long ull;

// ---------------- device scratch ----------------
__device__ float g_deg   [NMAX];
__device__ float g_dinv  [NMAX];
__device__ float g_tmp   [NMAX * 64];
__device__ float g_h1    [NMAX * 64];
__device__ float g_h2    [NMAX * 64];
__device__ float g_logits[NMAX * 32];
__device__ float g_wts   [NMAX];
__device__ int   g_rowptr[NMAX + 1];
__device__ int   g_fill  [NMAX];
__device__ int   g_csrc  [EMAX];
__device__ float g_pmin  [256];
__device__ float g_pmax  [256];
__device__ float g_minmax[2];
__device__ float g_acc   [33];

// ---------------- f32x2 packed helpers ----------------
__device__ __forceinline__ ull pack2(float a, float b) {
    ull r; unsigned ia = __float_as_uint(a), ib = __float_as_uint(b);
    asm("mov.b64 %0, {%1, %2};" : "=l"(r) : "r"(ia), "r"(ib));
    return r;
}
__device__ __forceinline__ void ffma2(ull& d, ull a, ull b) {
    asm("fma.rn.f32x2 %0, %1, %2, %0;" : "+l"(d) : "l"(a), "l"(b));
}
__device__ __forceinline__ float2 unp(ull v) {
    float2 r; unsigned lo = (unsigned)v, hi = (unsigned)(v >> 32);
    r.x = __uint_as_float(lo); r.y = __uint_as_float(hi);
    return r;
}

// ---------------- degree / normalization ----------------
__global__ void deg_init_k(int n) {
    int i = blockIdx.x * blockDim.x + threadIdx.x;
    if (i < n) g_deg[i] = 1.0f;   // self-loop
}
__global__ void deg_count_k(const int* __restrict__ dstI, int e) {
    int i = blockIdx.x * blockDim.x + threadIdx.x;
    if (i < e) atomicAdd(&g_deg[dstI[i]], 1.0f);
}
__global__ void dinv_k(int n) {
    int i = blockIdx.x * blockDim.x + threadIdx.x;
    if (i < n) g_dinv[i] = rsqrtf(g_deg[i]);
}

// ---------------- CSR build: rowptr prefix scan (1 block) + fill ----------------
__global__ void scan_k(int n) {
    __shared__ int sh[1024];
    int t = threadIdx.x;
    int chunk = (n + 1023) >> 10;
    int lo = t * chunk, hi = min(lo + chunk, n);
    int s = 0;
    for (int i = lo; i < hi; i++) s += (int)g_deg[i] - 1;   // edge count per node
    sh[t] = s;
    __syncthreads();
    for (int off = 1; off < 1024; off <<= 1) {
        int v = 0;
        if (t >= off) v = sh[t - off];
        __syncthreads();
        if (t >= off) sh[t] += v;
        __syncthreads();
    }
    int p = (t > 0) ? sh[t - 1] : 0;   // exclusive prefix
    for (int i = lo; i < hi; i++) {
        g_rowptr[i] = p;
        p += (int)g_deg[i] - 1;
        g_fill[i] = 0;
    }
    if (t == 1023) g_rowptr[n] = sh[1023];
}

__global__ void fill_k(const int* __restrict__ srcI,
                       const int* __restrict__ dstI, int e) {
    int i = blockIdx.x * blockDim.x + threadIdx.x;
    if (i >= e) return;
    int s = __ldg(srcI + i);
    int d = __ldg(dstI + i);
    int pos = atomicAdd(&g_fill[d], 1);
    g_csrc[g_rowptr[d] + pos] = s;
}

// ---------------- fused GEMM: [128-node tile] x [64x64 W] ----------------
// Thread tile 4 nodes x 8 outputs, f32x2-packed over output pairs.
// Writes only raw h -> g_tmp (propagation handled by gather_k).
// MODE 0: X = Xin. MODE 1: X = g_h1 with bias+BN+ReLU applied on load.
template<int MODE>
__global__ void __launch_bounds__(256) gemm_fused_k(
    const float* __restrict__ Xin,
    const float* __restrict__ W,
    const float* __restrict__ b1,
    const float* __restrict__ gamma,
    const float* __restrict__ beta,
    int n)
{
    __shared__ float4 Xs4[64 * 32];   // 32 KB : [k][node-group swizzled]
    __shared__ float4 Ws4[64 * 16];   // 16 KB : [k][j/4]
    const float* X = (MODE == 0) ? Xin : g_h1;
    int t  = threadIdx.x;
    int n0 = blockIdx.x * 128;

    const float4* W4 = (const float4*)W;
    for (int i = t; i < 1024; i += 256) Ws4[i] = W4[i];

    const float rs = rsqrtf(1.0f + 1e-5f);
    float* Xsf = (float*)Xs4;
    for (int i = t; i < 2048; i += 256) {
        int node = i >> 4, c4 = i & 15;
        int gn = n0 + node;
        float4 v = make_float4(0.f, 0.f, 0.f, 0.f);
        if (gn < n) {
            v = ((const float4*)(X + (size_t)gn * 64))[c4];
            if (MODE == 1) {
                float4 gm = ((const float4*)gamma)[c4];
                float4 bt = ((const float4*)beta )[c4];
                float4 bb = ((const float4*)b1   )[c4];
                float a0 = rs * gm.x, a1 = rs * gm.y, a2 = rs * gm.z, a3 = rs * gm.w;
                v.x = fmaxf(fmaf(v.x + bb.x, a0, bt.x), 0.f);
                v.y = fmaxf(fmaf(v.y + bb.y, a1, bt.y), 0.f);
                v.z = fmaxf(fmaf(v.z + bb.z, a2, bt.z), 0.f);
                v.w = fmaxf(fmaf(v.w + bb.w, a3, bt.w), 0.f);
            }
        }
        int g = node >> 2, lo = node & 3;
        int sg = g ^ (c4 & 7);
        float* base = Xsf + (c4 * 4) * 128 + sg * 4 + lo;
        base[0]   = v.x;
        base[128] = v.y;
        base[256] = v.z;
        base[384] = v.w;
    }
    __syncthreads();

    int ng = t & 31;        // node group (4 nodes)
    int og = t >> 5;        // output group (8 outputs) — uniform per warp
    ull acc2[4][4];         // [node][output pair] -> outputs (2jp, 2jp+1)
#pragma unroll
    for (int i = 0; i < 4; i++)
#pragma unroll
        for (int jp = 0; jp < 4; jp++) acc2[i][jp] = 0ull;

#pragma unroll 8
    for (int k = 0; k < 64; k++) {
        float4 xv = Xs4[k * 32 + (ng ^ ((k >> 2) & 7))];
        ulonglong2 wA = *(const ulonglong2*)&Ws4[k * 16 + og * 2];
        ulonglong2 wB = *(const ulonglong2*)&Ws4[k * 16 + og * 2 + 1];
        ull w2[4] = {wA.x, wA.y, wB.x, wB.y};
        float xa[4] = {xv.x, xv.y, xv.z, xv.w};
#pragma unroll
        for (int i = 0; i < 4; i++) {
            ull xd = pack2(xa[i], xa[i]);
#pragma unroll
            for (int jp = 0; jp < 4; jp++) ffma2(acc2[i][jp], xd, w2[jp]);
        }
    }

    int nb = n0 + 4 * ng;
#pragma unroll
    for (int i = 0; i < 4; i++) {
        int gn = nb + i;
        if (gn < n) {
            float2 p0 = unp(acc2[i][0]), p1 = unp(acc2[i][1]);
            float2 p2 = unp(acc2[i][2]), p3 = unp(acc2[i][3]);
            float4* tp = (float4*)(g_tmp + (size_t)gn * 64 + og * 8);
            tp[0] = make_float4(p0.x, p0.y, p1.x, p1.y);
            tp[1] = make_float4(p2.x, p2.y, p3.x, p3.y);
        }
    }
}

// ---------------- CSR gather: out[d] = tmp[d]*dinv[d]^2 + sum tmp[s]*dinv[s]*dinv[d] ----
__global__ void __launch_bounds__(256) gather_k(int which, int n) {
    int g = (blockIdx.x * blockDim.x + threadIdx.x) >> 4;
    int c = threadIdx.x & 15;
    if (g >= n) return;
    float dd = g_dinv[g];
    float4 acc = ((const float4*)(g_tmp + (size_t)g * 64))[c];
    float s2 = dd * dd;
    acc.x *= s2; acc.y *= s2; acc.z *= s2; acc.w *= s2;
    int j = g_rowptr[g], end = g_rowptr[g + 1];
    for (; j + 1 < end; j += 2) {
        int s0 = __ldg(g_csrc + j);
        int s1 = __ldg(g_csrc + j + 1);
        float n0 = g_dinv[s0] * dd;
        float n1 = g_dinv[s1] * dd;
        float4 v0 = ((const float4*)(g_tmp + (size_t)s0 * 64))[c];
        float4 v1 = ((const float4*)(g_tmp + (size_t)s1 * 64))[c];
        acc.x = fmaf(v0.x, n0, fmaf(v1.x, n1, acc.x));
        acc.y = fmaf(v0.y, n0, fmaf(v1.y, n1, acc.y));
        acc.z = fmaf(v0.z, n0, fmaf(v1.z, n1, acc.z));
        acc.w = fmaf(v0.w, n0, fmaf(v1.w, n1, acc.w));
    }
    if (j < end) {
        int s0 = __ldg(g_csrc + j);
        float n0 = g_dinv[s0] * dd;
        float4 v0 = ((const float4*)(g_tmp + (size_t)s0 * 64))[c];
        acc.x = fmaf(v0.x, n0, acc.x);
        acc.y = fmaf(v0.y, n0, acc.y);
        acc.z = fmaf(v0.z, n0, acc.z);
        acc.w = fmaf(v0.w, n0, acc.w);
    }
    float* outp = which ? g_h2 : g_h1;
    ((float4*)(outp + (size_t)g * 64))[c] = acc;
}

// ---------------- logits + softmax + entropy + wts ----------------
__global__ void __launch_bounds__(128) logits_k(
    const float* __restrict__ b2,
    const float* __restrict__ W,    // [64,32] row-major
    const float* __restrict__ bb,   // [32]
    int n)
{
    __shared__ float4 Xs4[64 * 32];  // 32 KB, reused for Ls after sync
    __shared__ float4 Wl4[64 * 8];   // 8 KB
    int t  = threadIdx.x;
    int n0 = blockIdx.x * 128;

    for (int i = t; i < 512; i += 128) Wl4[i] = ((const float4*)W)[i];

    float* Xsf = (float*)Xs4;
    for (int i = t; i < 2048; i += 128) {
        int node = i >> 4, c4 = i & 15;
        int gn = n0 + node;
        float4 v = make_float4(0.f, 0.f, 0.f, 0.f);
        if (gn < n) {
            v = ((const float4*)(g_h2 + (size_t)gn * 64))[c4];
            float4 b = ((const float4*)b2)[c4];
            v.x += b.x; v.y += b.y; v.z += b.z; v.w += b.w;
        }
        int g = node >> 2, lo = node & 3;
        int sg = g ^ (c4 & 7);
        float* base = Xsf + (c4 * 4) * 128 + sg * 4 + lo;
        base[0]   = v.x;
        base[128] = v.y;
        base[256] = v.z;
        base[384] = v.w;
    }
    __syncthreads();

    int ng = t & 31;
    int og = t >> 5;   // 0..3, uniform per warp
    ull acc2[4][4];
    float4 bb0 = ((const float4*)bb)[og * 2];
    float4 bb1 = ((const float4*)bb)[og * 2 + 1];
    float bj[8] = {bb0.x, bb0.y, bb0.z, bb0.w, bb1.x, bb1.y, bb1.z, bb1.w};
#pragma unroll
    for (int i = 0; i < 4; i++)
#pragma unroll
        for (int jp = 0; jp < 4; jp++) acc2[i][jp] = pack2(bj[2 * jp], bj[2 * jp + 1]);

#pragma unroll 8
    for (int k = 0; k < 64; k++) {
        float4 xv = Xs4[k * 32 + (ng ^ ((k >> 2) & 7))];
        ulonglong2 wA = *(const ulonglong2*)&Wl4[k * 8 + og * 2];
        ulonglong2 wB = *(const ulonglong2*)&Wl4[k * 8 + og * 2 + 1];
        ull w2[4] = {wA.x, wA.y, wB.x, wB.y};
        float xa[4] = {xv.x, xv.y, xv.z, xv.w};
#pragma unroll
        for (int i = 0; i < 4; i++) {
            ull xd = pack2(xa[i], xa[i]);
#pragma unroll
            for (int jp = 0; jp < 4; jp++) ffma2(acc2[i][jp], xd, w2[jp]);
        }
    }
    __syncthreads();   // done reading Xs — reuse as Ls[128][33]

    float* Ls = Xsf;
#pragma unroll
    for (int i = 0; i < 4; i++) {
        float2 p0 = unp(acc2[i][0]), p1 = unp(acc2[i][1]);
        float2 p2 = unp(acc2[i][2]), p3 = unp(acc2[i][3]);
        float* row = Ls + (4 * ng + i) * 33 + og * 8;
        row[0] = p0.x; row[1] = p0.y; row[2] = p1.x; row[3] = p1.y;
        row[4] = p2.x; row[5] = p2.y; row[6] = p3.x; row[7] = p3.y;
    }
    __syncthreads();

    int lane = t & 31;
    for (int r = og; r < 128; r += 4) {
        int gn = n0 + r;
        float l = Ls[r * 33 + lane];
        float m = l;
#pragma unroll
        for (int off = 16; off; off >>= 1)
            m = fmaxf(m, __shfl_xor_sync(0xffffffffu, m, off));
        float p = expf(l - m);
        float sum = p;
#pragma unroll
        for (int off = 16; off; off >>= 1)
            sum += __shfl_xor_sync(0xffffffffu, sum, off);
        p /= sum;
        float term = -p * logf(p + 1e-9f);
#pragma unroll
        for (int off = 16; off; off >>= 1)
            term += __shfl_xor_sync(0xffffffffu, term, off);
        if (gn < n) {
            g_logits[(size_t)gn * 32 + lane] = l;
            if (lane == 0) g_wts[gn] = 1.0f / (term + 1e-10f);
        }
    }
}

// ---------------- min/max reduction of wts ----------------
__global__ void mm_part_k(int n) {
    __shared__ float smn[256], smx[256];
    int t = threadIdx.x;
    float mn = 3.4e38f, mx = -3.4e38f;
    for (int i = blockIdx.x * 256 + t; i < n; i += 256 * gridDim.x) {
        float w = g_wts[i];
        mn = fminf(mn, w); mx = fmaxf(mx, w);
    }
    smn[t] = mn; smx[t] = mx;
    __syncthreads();
    for (int s = 128; s; s >>= 1) {
        if (t < s) { smn[t] = fminf(smn[t], smn[t + s]); smx[t] = fmaxf(smx[t], smx[t + s]); }
        __syncthreads();
    }
    if (t == 0) { g_pmin[blockIdx.x] = smn[0]; g_pmax[blockIdx.x] = smx[0]; }
}

__global__ void mm_final_k() {
    __shared__ float smn[256], smx[256];
    int t = threadIdx.x;
    smn[t] = g_pmin[t]; smx[t] = g_pmax[t];
    if (t < 33) g_acc[t] = 0.0f;
    __syncthreads();
    for (int s = 128; s; s >>= 1) {
        if (t < s) { smn[t] = fminf(smn[t], smn[t + s]); smx[t] = fmaxf(smx[t], smx[t + s]); }
        __syncthreads();
    }
    if (t == 0) { g_minmax[0] = smn[0]; g_minmax[1] = smx[0]; }
}

// ---------------- weighted sum ----------------
__global__ void wsum_k(int n) {
    __shared__ float sacc[8][33];
    int t = threadIdx.x, w = t >> 5, lane = t & 31;
    float mn = g_minmax[0];
    float den = g_minmax[1] - mn;
    float inv = den > 0.0f ? 1.0f / den : 0.0f;
    float acc = 0.0f, se = 0.0f;
    int warpG = blockIdx.x * 8 + w;
    int nwarp = gridDim.x * 8;
    for (int i = warpG; i < n; i += nwarp) {
        float e = expf((g_wts[i] - mn) * inv);
        acc += e * g_logits[(size_t)i * 32 + lane];
        se  += e;
    }
    sacc[w][lane] = acc;
    if (lane == 0) sacc[w][32] = se;
    __syncthreads();
    if (w == 0) {
        float a = sacc[0][lane];
#pragma unroll
        for (int r = 1; r < 8; r++) a += sacc[r][lane];
        atomicAdd(&g_acc[lane], a);
        if (lane == 0) {
            float b = sacc[0][32];
#pragma unroll
            for (int r = 1; r < 8; r++) b += sacc[r][32];
            atomicAdd(&g_acc[32], b);
        }
    }
}

// ---------------- final ----------------
__global__ void final_k(const float* __restrict__ w3,
                        const float* __restrict__ b3,
                        float* __restrict__ out) {
    int j = threadIdx.x;
    float invS = 1.0f / g_acc[32];
    float a = b3[j];
#pragma unroll
    for (int o = 0; o < 32; o++) a += (g_acc[o] * invS) * w3[o * 64 + j];
    out[j] = a;
}

// ---------------- launch ----------------
extern "C" void kernel_launch(void* const* d_in, const int* in_sizes, int n_in,
                              void* d_out, int out_size) {
    const float* x     = (const float*)d_in[0];
    const int*   ei    = (const int*)  d_in[1];
    const float* W1    = (const float*)d_in[2];
    const float* b1    = (const float*)d_in[3];
    const float* gamma = (const float*)d_in[4];
    const float* beta  = (const float*)d_in[5];
    const float* W2    = (const float*)d_in[6];
    const float* b2    = (const float*)d_in[7];
    const float* l2w   = (const float*)d_in[8];
    const float* l2b   = (const float*)d_in[9];
    const float* l3w   = (const float*)d_in[10];
    const float* l3b   = (const float*)d_in[11];
    float* out = (float*)d_out;

    int n = in_sizes[0] / 64;
    int e = in_sizes[1] / 2;
    const int* srcI = ei;
    const int* dstI = ei + e;

    int nb  = (n + 255) / 256;
    int eb  = (e + 255) / 256;
    int gb  = (n + 127) / 128;
    int gtb = (n * 16 + 255) / 256;

    deg_init_k <<<nb, 256>>>(n);
    deg_count_k<<<eb, 256>>>(dstI, e);
    dinv_k     <<<nb, 256>>>(n);
    scan_k     <<<1, 1024>>>(n);
    fill_k     <<<eb, 256>>>(srcI, dstI, e);

    // layer 1
    gemm_fused_k<0><<<gb, 256>>>(x, W1, nullptr, nullptr, nullptr, n);
    gather_k       <<<gtb, 256>>>(0, n);

    // layer 2 (bias+BN+ReLU fused into loader)
    gemm_fused_k<1><<<gb, 256>>>(nullptr, W2, b1, gamma, beta, n);
    gather_k       <<<gtb, 256>>>(1, n);

    // readout
    logits_k  <<<gb, 128>>>(b2, l2w, l2b, n);
    mm_part_k <<<256, 256>>>(n);
    mm_final_k<<<1, 256>>>();
    wsum_k    <<<128, 256>>>(n);
    final_k   <<<1, 64>>>(l3w, l3b, out);
}

// round 5
// speedup vs baseline: 1.6175x; 1.6175x over previous
#include <cuda_runtime.h>

#define NMAX 100000
#define EMAX 1600000

typedef unsigned long long ull;

// ---------------- device scratch ----------------
__device__ float g_deg   [NMAX];
__device__ float g_dinv  [NMAX];
__device__ float g_tmp   [NMAX * 64];
__device__ float g_h1    [NMAX * 64];
__device__ float g_h2    [NMAX * 64];
__device__ float g_logits[NMAX * 32];
__device__ float g_wts   [NMAX];
__device__ int   g_rowptr[NMAX + 1];
__device__ int   g_fill  [NMAX];
__device__ int   g_csrc  [EMAX];
__device__ int   g_bsum  [64];
__device__ int   g_boff  [64];
__device__ float g_pmin  [256];
__device__ float g_pmax  [256];
__device__ float g_minmax[2];
__device__ float g_acc   [33];

// ---------------- f32x2 packed helpers ----------------
__device__ __forceinline__ ull pack2(float a, float b) {
    ull r; unsigned ia = __float_as_uint(a), ib = __float_as_uint(b);
    asm("mov.b64 %0, {%1, %2};" : "=l"(r) : "r"(ia), "r"(ib));
    return r;
}
__device__ __forceinline__ void ffma2(ull& d, ull a, ull b) {
    asm("fma.rn.f32x2 %0, %1, %2, %0;" : "+l"(d) : "l"(a), "l"(b));
}
__device__ __forceinline__ float2 unp(ull v) {
    float2 r; unsigned lo = (unsigned)v, hi = (unsigned)(v >> 32);
    r.x = __uint_as_float(lo); r.y = __uint_as_float(hi);
    return r;
}

// ---------------- degree ----------------
__global__ void deg_init_k(int n) {
    int i = blockIdx.x * blockDim.x + threadIdx.x;
    if (i < n) g_deg[i] = 1.0f;   // self-loop
}
__global__ void deg_count_k(const int* __restrict__ dstI, int e) {
    int i = blockIdx.x * blockDim.x + threadIdx.x;
    if (i < e) atomicAdd(&g_deg[dstI[i]], 1.0f);
}

// ---------------- parallel CSR rowptr scan (3 stages) ----------------
// stage 1: per-block exclusive scan (2048 nodes/block); also computes dinv.
__global__ void __launch_bounds__(256) scan1_k(int n) {
    __shared__ int wsum[8];
    int t = threadIdx.x;
    int base = blockIdx.x * 2048 + t * 8;
    int d[8]; int s = 0;
#pragma unroll
    for (int i = 0; i < 8; i++) {
        int idx = base + i;
        float dg = (idx < n) ? g_deg[idx] : 1.0f;
        if (idx < n) g_dinv[idx] = rsqrtf(dg);
        d[i] = (idx < n) ? (int)dg - 1 : 0;   // edges into this node
        s += d[i];
    }
    int lane = t & 31, w = t >> 5;
    int inc = s;
#pragma unroll
    for (int off = 1; off < 32; off <<= 1) {
        int v = __shfl_up_sync(0xffffffffu, inc, off);
        if (lane >= off) inc += v;
    }
    if (lane == 31) wsum[w] = inc;
    __syncthreads();
    if (w == 0) {
        int v = (lane < 8) ? wsum[lane] : 0;
#pragma unroll
        for (int off = 1; off < 8; off <<= 1) {
            int u = __shfl_up_sync(0xffffffffu, v, off);
            if (lane >= off) v += u;
        }
        if (lane < 8) wsum[lane] = v;
    }
    __syncthreads();
    int exc = inc - s + (w > 0 ? wsum[w - 1] : 0);
#pragma unroll
    for (int i = 0; i < 8; i++) {
        int idx = base + i;
        if (idx < n) { g_rowptr[idx] = exc; g_fill[idx] = 0; }
        exc += d[i];
    }
    if (t == 255) g_bsum[blockIdx.x] = wsum[7];
}

// stage 2: 1 warp scans the <=64 block sums -> exclusive offsets + rowptr[n].
__global__ void scan2_k(int nb, int n) {
    int lane = threadIdx.x;
    int a = (lane      < nb) ? g_bsum[lane]      : 0;
    int b = (lane + 32 < nb) ? g_bsum[lane + 32] : 0;
    int ia = a, ib = b;
#pragma unroll
    for (int off = 1; off < 32; off <<= 1) {
        int v = __shfl_up_sync(0xffffffffu, ia, off);
        if (lane >= off) ia += v;
        int u = __shfl_up_sync(0xffffffffu, ib, off);
        if (lane >= off) ib += u;
    }
    int sumA = __shfl_sync(0xffffffffu, ia, 31);
    g_boff[lane]      = ia - a;
    g_boff[lane + 32] = sumA + ib - b;
    if (lane == 31) g_rowptr[n] = sumA + ib;
}

// stage 3: add block offsets.
__global__ void __launch_bounds__(256) scan3_k(int n) {
    int add = g_boff[blockIdx.x];
    int base = blockIdx.x * 2048 + threadIdx.x * 8;
#pragma unroll
    for (int i = 0; i < 8; i++) {
        int idx = base + i;
        if (idx < n) g_rowptr[idx] += add;
    }
}

__global__ void fill_k(const int* __restrict__ srcI,
                       const int* __restrict__ dstI, int e) {
    int i = blockIdx.x * blockDim.x + threadIdx.x;
    if (i >= e) return;
    int s = __ldg(srcI + i);
    int d = __ldg(dstI + i);
    int pos = atomicAdd(&g_fill[d], 1);
    g_csrc[g_rowptr[d] + pos] = s;
}

// ---------------- fused GEMM: [128-node tile] x [64x64 W] ----------------
template<int MODE>
__global__ void __launch_bounds__(256) gemm_fused_k(
    const float* __restrict__ Xin,
    const float* __restrict__ W,
    const float* __restrict__ b1,
    const float* __restrict__ gamma,
    const float* __restrict__ beta,
    int n)
{
    __shared__ float4 Xs4[64 * 32];   // 32 KB : [k][node-group swizzled]
    __shared__ float4 Ws4[64 * 16];   // 16 KB : [k][j/4]
    const float* X = (MODE == 0) ? Xin : g_h1;
    int t  = threadIdx.x;
    int n0 = blockIdx.x * 128;

    const float4* W4 = (const float4*)W;
    for (int i = t; i < 1024; i += 256) Ws4[i] = W4[i];

    const float rs = rsqrtf(1.0f + 1e-5f);
    float* Xsf = (float*)Xs4;
    for (int i = t; i < 2048; i += 256) {
        int node = i >> 4, c4 = i & 15;
        int gn = n0 + node;
        float4 v = make_float4(0.f, 0.f, 0.f, 0.f);
        if (gn < n) {
            v = ((const float4*)(X + (size_t)gn * 64))[c4];
            if (MODE == 1) {
                float4 gm = ((const float4*)gamma)[c4];
                float4 bt = ((const float4*)beta )[c4];
                float4 bb = ((const float4*)b1   )[c4];
                float a0 = rs * gm.x, a1 = rs * gm.y, a2 = rs * gm.z, a3 = rs * gm.w;
                v.x = fmaxf(fmaf(v.x + bb.x, a0, bt.x), 0.f);
                v.y = fmaxf(fmaf(v.y + bb.y, a1, bt.y), 0.f);
                v.z = fmaxf(fmaf(v.z + bb.z, a2, bt.z), 0.f);
                v.w = fmaxf(fmaf(v.w + bb.w, a3, bt.w), 0.f);
            }
        }
        int g = node >> 2, lo = node & 3;
        int sg = g ^ (c4 & 7);
        float* base = Xsf + (c4 * 4) * 128 + sg * 4 + lo;
        base[0]   = v.x;
        base[128] = v.y;
        base[256] = v.z;
        base[384] = v.w;
    }
    __syncthreads();

    int ng = t & 31;
    int og = t >> 5;
    ull acc2[4][4];
#pragma unroll
    for (int i = 0; i < 4; i++)
#pragma unroll
        for (int jp = 0; jp < 4; jp++) acc2[i][jp] = 0ull;

#pragma unroll 8
    for (int k = 0; k < 64; k++) {
        float4 xv = Xs4[k * 32 + (ng ^ ((k >> 2) & 7))];
        ulonglong2 wA = *(const ulonglong2*)&Ws4[k * 16 + og * 2];
        ulonglong2 wB = *(const ulonglong2*)&Ws4[k * 16 + og * 2 + 1];
        ull w2[4] = {wA.x, wA.y, wB.x, wB.y};
        float xa[4] = {xv.x, xv.y, xv.z, xv.w};
#pragma unroll
        for (int i = 0; i < 4; i++) {
            ull xd = pack2(xa[i], xa[i]);
#pragma unroll
            for (int jp = 0; jp < 4; jp++) ffma2(acc2[i][jp], xd, w2[jp]);
        }
    }

    int nb = n0 + 4 * ng;
#pragma unroll
    for (int i = 0; i < 4; i++) {
        int gn = nb + i;
        if (gn < n) {
            float2 p0 = unp(acc2[i][0]), p1 = unp(acc2[i][1]);
            float2 p2 = unp(acc2[i][2]), p3 = unp(acc2[i][3]);
            float4* tp = (float4*)(g_tmp + (size_t)gn * 64 + og * 8);
            tp[0] = make_float4(p0.x, p0.y, p1.x, p1.y);
            tp[1] = make_float4(p2.x, p2.y, p3.x, p3.y);
        }
    }
}

// ---------------- CSR gather ----------------
__global__ void __launch_bounds__(256) gather_k(int which, int n) {
    int g = (blockIdx.x * blockDim.x + threadIdx.x) >> 4;
    int c = threadIdx.x & 15;
    if (g >= n) return;
    float dd = g_dinv[g];
    float4 acc = ((const float4*)(g_tmp + (size_t)g * 64))[c];
    float s2 = dd * dd;
    acc.x *= s2; acc.y *= s2; acc.z *= s2; acc.w *= s2;
    int j = g_rowptr[g], end = g_rowptr[g + 1];
    for (; j + 1 < end; j += 2) {
        int s0 = __ldg(g_csrc + j);
        int s1 = __ldg(g_csrc + j + 1);
        float n0 = g_dinv[s0] * dd;
        float n1 = g_dinv[s1] * dd;
        float4 v0 = ((const float4*)(g_tmp + (size_t)s0 * 64))[c];
        float4 v1 = ((const float4*)(g_tmp + (size_t)s1 * 64))[c];
        acc.x = fmaf(v0.x, n0, fmaf(v1.x, n1, acc.x));
        acc.y = fmaf(v0.y, n0, fmaf(v1.y, n1, acc.y));
        acc.z = fmaf(v0.z, n0, fmaf(v1.z, n1, acc.z));
        acc.w = fmaf(v0.w, n0, fmaf(v1.w, n1, acc.w));
    }
    if (j < end) {
        int s0 = __ldg(g_csrc + j);
        float n0 = g_dinv[s0] * dd;
        float4 v0 = ((const float4*)(g_tmp + (size_t)s0 * 64))[c];
        acc.x = fmaf(v0.x, n0, acc.x);
        acc.y = fmaf(v0.y, n0, acc.y);
        acc.z = fmaf(v0.z, n0, acc.z);
        acc.w = fmaf(v0.w, n0, acc.w);
    }
    float* outp = which ? g_h2 : g_h1;
    ((float4*)(outp + (size_t)g * 64))[c] = acc;
}

// ---------------- logits + softmax + entropy + wts ----------------
__global__ void __launch_bounds__(128) logits_k(
    const float* __restrict__ b2,
    const float* __restrict__ W,    // [64,32] row-major
    const float* __restrict__ bb,   // [32]
    int n)
{
    __shared__ float4 Xs4[64 * 32];
    __shared__ float4 Wl4[64 * 8];
    int t  = threadIdx.x;
    int n0 = blockIdx.x * 128;

    for (int i = t; i < 512; i += 128) Wl4[i] = ((const float4*)W)[i];

    float* Xsf = (float*)Xs4;
    for (int i = t; i < 2048; i += 128) {
        int node = i >> 4, c4 = i & 15;
        int gn = n0 + node;
        float4 v = make_float4(0.f, 0.f, 0.f, 0.f);
        if (gn < n) {
            v = ((const float4*)(g_h2 + (size_t)gn * 64))[c4];
            float4 b = ((const float4*)b2)[c4];
            v.x += b.x; v.y += b.y; v.z += b.z; v.w += b.w;
        }
        int g = node >> 2, lo = node & 3;
        int sg = g ^ (c4 & 7);
        float* base = Xsf + (c4 * 4) * 128 + sg * 4 + lo;
        base[0]   = v.x;
        base[128] = v.y;
        base[256] = v.z;
        base[384] = v.w;
    }
    __syncthreads();

    int ng = t & 31;
    int og = t >> 5;
    ull acc2[4][4];
    float4 bb0 = ((const float4*)bb)[og * 2];
    float4 bb1 = ((const float4*)bb)[og * 2 + 1];
    float bj[8] = {bb0.x, bb0.y, bb0.z, bb0.w, bb1.x, bb1.y, bb1.z, bb1.w};
#pragma unroll
    for (int i = 0; i < 4; i++)
#pragma unroll
        for (int jp = 0; jp < 4; jp++) acc2[i][jp] = pack2(bj[2 * jp], bj[2 * jp + 1]);

#pragma unroll 8
    for (int k = 0; k < 64; k++) {
        float4 xv = Xs4[k * 32 + (ng ^ ((k >> 2) & 7))];
        ulonglong2 wA = *(const ulonglong2*)&Wl4[k * 8 + og * 2];
        ulonglong2 wB = *(const ulonglong2*)&Wl4[k * 8 + og * 2 + 1];
        ull w2[4] = {wA.x, wA.y, wB.x, wB.y};
        float xa[4] = {xv.x, xv.y, xv.z, xv.w};
#pragma unroll
        for (int i = 0; i < 4; i++) {
            ull xd = pack2(xa[i], xa[i]);
#pragma unroll
            for (int jp = 0; jp < 4; jp++) ffma2(acc2[i][jp], xd, w2[jp]);
        }
    }
    __syncthreads();

    float* Ls = Xsf;
#pragma unroll
    for (int i = 0; i < 4; i++) {
        float2 p0 = unp(acc2[i][0]), p1 = unp(acc2[i][1]);
        float2 p2 = unp(acc2[i][2]), p3 = unp(acc2[i][3]);
        float* row = Ls + (4 * ng + i) * 33 + og * 8;
        row[0] = p0.x; row[1] = p0.y; row[2] = p1.x; row[3] = p1.y;
        row[4] = p2.x; row[5] = p2.y; row[6] = p3.x; row[7] = p3.y;
    }
    __syncthreads();

    int lane = t & 31;
    for (int r = og; r < 128; r += 4) {
        int gn = n0 + r;
        float l = Ls[r * 33 + lane];
        float m = l;
#pragma unroll
        for (int off = 16; off; off >>= 1)
            m = fmaxf(m, __shfl_xor_sync(0xffffffffu, m, off));
        float p = expf(l - m);
        float sum = p;
#pragma unroll
        for (int off = 16; off; off >>= 1)
            sum += __shfl_xor_sync(0xffffffffu, sum, off);
        p /= sum;
        float term = -p * logf(p + 1e-9f);
#pragma unroll
        for (int off = 16; off; off >>= 1)
            term += __shfl_xor_sync(0xffffffffu, term, off);
        if (gn < n) {
            g_logits[(size_t)gn * 32 + lane] = l;
            if (lane == 0) g_wts[gn] = 1.0f / (term + 1e-10f);
        }
    }
}

// ---------------- min/max reduction of wts ----------------
__global__ void mm_part_k(int n) {
    __shared__ float smn[256], smx[256];
    int t = threadIdx.x;
    float mn = 3.4e38f, mx = -3.4e38f;
    for (int i = blockIdx.x * 256 + t; i < n; i += 256 * gridDim.x) {
        float w = g_wts[i];
        mn = fminf(mn, w); mx = fmaxf(mx, w);
    }
    smn[t] = mn; smx[t] = mx;
    __syncthreads();
    for (int s = 128; s; s >>= 1) {
        if (t < s) { smn[t] = fminf(smn[t], smn[t + s]); smx[t] = fmaxf(smx[t], smx[t + s]); }
        __syncthreads();
    }
    if (t == 0) { g_pmin[blockIdx.x] = smn[0]; g_pmax[blockIdx.x] = smx[0]; }
}

__global__ void mm_final_k() {
    __shared__ float smn[256], smx[256];
    int t = threadIdx.x;
    smn[t] = g_pmin[t]; smx[t] = g_pmax[t];
    if (t < 33) g_acc[t] = 0.0f;
    __syncthreads();
    for (int s = 128; s; s >>= 1) {
        if (t < s) { smn[t] = fminf(smn[t], smn[t + s]); smx[t] = fmaxf(smx[t], smx[t + s]); }
        __syncthreads();
    }
    if (t == 0) { g_minmax[0] = smn[0]; g_minmax[1] = smx[0]; }
}

// ---------------- weighted sum ----------------
__global__ void wsum_k(int n) {
    __shared__ float sacc[8][33];
    int t = threadIdx.x, w = t >> 5, lane = t & 31;
    float mn = g_minmax[0];
    float den = g_minmax[1] - mn;
    float inv = den > 0.0f ? 1.0f / den : 0.0f;
    float acc = 0.0f, se = 0.0f;
    int warpG = blockIdx.x * 8 + w;
    int nwarp = gridDim.x * 8;
    for (int i = warpG; i < n; i += nwarp) {
        float e = expf((g_wts[i] - mn) * inv);
        acc += e * g_logits[(size_t)i * 32 + lane];
        se  += e;
    }
    sacc[w][lane] = acc;
    if (lane == 0) sacc[w][32] = se;
    __syncthreads();
    if (w == 0) {
        float a = sacc[0][lane];
#pragma unroll
        for (int r = 1; r < 8; r++) a += sacc[r][lane];
        atomicAdd(&g_acc[lane], a);
        if (lane == 0) {
            float b = sacc[0][32];
#pragma unroll
            for (int r = 1; r < 8; r++) b += sacc[r][32];
            atomicAdd(&g_acc[32], b);
        }
    }
}

// ---------------- final ----------------
__global__ void final_k(const float* __restrict__ w3,
                        const float* __restrict__ b3,
                        float* __restrict__ out) {
    int j = threadIdx.x;
    float invS = 1.0f / g_acc[32];
    float a = b3[j];
#pragma unroll
    for (int o = 0; o < 32; o++) a += (g_acc[o] * invS) * w3[o * 64 + j];
    out[j] = a;
}

// ---------------- launch ----------------
extern "C" void kernel_launch(void* const* d_in, const int* in_sizes, int n_in,
                              void* d_out, int out_size) {
    const float* x     = (const float*)d_in[0];
    const int*   ei    = (const int*)  d_in[1];
    const float* W1    = (const float*)d_in[2];
    const float* b1    = (const float*)d_in[3];
    const float* gamma = (const float*)d_in[4];
    const float* beta  = (const float*)d_in[5];
    const float* W2    = (const float*)d_in[6];
    const float* b2    = (const float*)d_in[7];
    const float* l2w   = (const float*)d_in[8];
    const float* l2b   = (const float*)d_in[9];
    const float* l3w   = (const float*)d_in[10];
    const float* l3b   = (const float*)d_in[11];
    float* out = (float*)d_out;

    int n = in_sizes[0] / 64;
    int e = in_sizes[1] / 2;
    const int* srcI = ei;
    const int* dstI = ei + e;

    int nb  = (n + 255) / 256;
    int eb  = (e + 255) / 256;
    int gb  = (n + 127) / 128;
    int gtb = (n * 16 + 255) / 256;
    int scb = (n + 2047) / 2048;

    deg_init_k <<<nb, 256>>>(n);
    deg_count_k<<<eb, 256>>>(dstI, e);
    scan1_k    <<<scb, 256>>>(n);
    scan2_k    <<<1, 32>>>(scb, n);
    scan3_k    <<<scb, 256>>>(n);
    fill_k     <<<eb, 256>>>(srcI, dstI, e);

    // layer 1
    gemm_fused_k<0><<<gb, 256>>>(x, W1, nullptr, nullptr, nullptr, n);
    gather_k       <<<gtb, 256>>>(0, n);

    // layer 2 (bias+BN+ReLU fused into loader)
    gemm_fused_k<1><<<gb, 256>>>(nullptr, W2, b1, gamma, beta, n);
    gather_k       <<<gtb, 256>>>(1, n);

    // readout
    logits_k  <<<gb, 128>>>(b2, l2w, l2b, n);
    mm_part_k <<<256, 256>>>(n);
    mm_final_k<<<1, 256>>>();
    wsum_k    <<<128, 256>>>(n);
    final_k   <<<1, 64>>>(l3w, l3b, out);
}